// round 1
// baseline (speedup 1.0000x reference)
#include <cuda_runtime.h>
#include <cuda_bf16.h>
#include <math.h>

// Problem constants
#define B_     8192
#define OBS_   128
#define LAT_   32
#define NXT_   128
#define E_     8
#define HG_    256
#define H_     256
#define DIN_   (OBS_ + LAT_)   // 160
#define IN1_   (H_ + LAT_)     // 288

// ---------------- device scratch (no allocs allowed) ----------------
__device__ float g_xz [B_ * DIN_];   // [B,160] concat(x,z)
__device__ float g_g0 [B_ * HG_];    // gating hidden 1
__device__ float g_g1 [B_ * HG_];    // gating hidden 2
__device__ float g_g2 [B_ * HG_];    // gating hidden 3
__device__ float g_h1 [B_ * IN1_];   // [B,288] = [h0 | z]
__device__ float g_h2 [B_ * IN1_];   // [B,288] = [h1 | z]
__device__ float g_coef[B_ * E_];    // softmax coefficients

// ---------------- pack kernel: build xz and z-tails ----------------
__global__ void pack_kernel(const float* __restrict__ x, const float* __restrict__ z)
{
    int stride = gridDim.x * blockDim.x;
    int idx = blockIdx.x * blockDim.x + threadIdx.x;
    // xz
    for (int t = idx; t < B_ * DIN_; t += stride) {
        int b = t / DIN_, c = t - b * DIN_;
        g_xz[t] = (c < OBS_) ? x[b * OBS_ + c] : z[b * LAT_ + (c - OBS_)];
    }
    // z tails of h1/h2 (cols 256..287)
    for (int t = idx; t < B_ * LAT_; t += stride) {
        int b = t / LAT_, c = t - b * LAT_;
        float v = z[t];
        g_h1[b * IN1_ + H_ + c] = v;
        g_h2[b * IN1_ + H_ + c] = v;
    }
}

// ---------------- generic tiled SGEMM ----------------
// C[M,N] = act( A'[M,K] @ W[K,N] + bias_term )
// EXPERT mode: A'(b, k=e*IN+i) = coef[b,e] * A[b*lda + i]
//              bias_term(b,o)  = sum_e coef[b,e] * bias[e*N + o]
// Plain mode : A'(b,k) = A[b*lda + k]; bias_term(o) = bias[o]
// ACT: 1 = ELU, 0 = identity
template<int BM, int BN, int BK, bool EXPERT, int IN, int ACT>
__global__ __launch_bounds__(256)
void gemm_kernel(const float* __restrict__ A, int lda,
                 const float* __restrict__ W,
                 const float* __restrict__ bias,
                 const float* __restrict__ coef,
                 float* __restrict__ C, int ldc,
                 int M, int N, int K)
{
    constexpr int TM = 4, TN = 4;
    __shared__ float As[BK][BM];
    __shared__ float Bs[BK][BN];
    __shared__ float coef_s[EXPERT ? BM * E_ : 1];
    __shared__ float bias_s[EXPERT ? E_ * BN : 1];

    const int tid = threadIdx.x;                 // 256 threads
    const int tx  = tid & ((BN / TN) - 1);       // 0..15
    const int ty  = tid / (BN / TN);             // 0..15
    const int rowBase = blockIdx.y * BM;
    const int colBase = blockIdx.x * BN;

    // staging indices
    const int arow  = tid >> 2;          // 0..63
    const int ak4   = (tid & 3) * 4;     // 0,4,8,12
    const int brow  = tid >> 4;          // 0..15
    const int bcol4 = (tid & 15) * 4;    // 0..60

    if constexpr (EXPERT) {
        for (int i = tid; i < BM * E_; i += 256)
            coef_s[i] = coef[rowBase * E_ + i];
        for (int i = tid; i < E_ * BN; i += 256)
            bias_s[i] = bias[(i / BN) * N + colBase + (i % BN)];
        __syncthreads();
    }

    float acc[TM][TN] = {};

    for (int kt = 0; kt < K; kt += BK) {
        float4 av, bv;
        if constexpr (EXPERT) {
            // whole BK-slice lies in a single expert (IN % BK == 0)
            int e  = kt / IN;
            int i0 = kt - e * IN + ak4;
            av = *(const float4*)(A + (size_t)(rowBase + arow) * lda + i0);
            float s = coef_s[arow * E_ + e];
            av.x *= s; av.y *= s; av.z *= s; av.w *= s;
        } else {
            av = *(const float4*)(A + (size_t)(rowBase + arow) * lda + kt + ak4);
        }
        bv = *(const float4*)(W + (size_t)(kt + brow) * N + colBase + bcol4);

        __syncthreads();
        As[ak4 + 0][arow] = av.x;
        As[ak4 + 1][arow] = av.y;
        As[ak4 + 2][arow] = av.z;
        As[ak4 + 3][arow] = av.w;
        *(float4*)&Bs[brow][bcol4] = bv;
        __syncthreads();

#pragma unroll
        for (int k = 0; k < BK; k++) {
            float4 a4 = *(const float4*)&As[k][ty * TM];
            float4 b4 = *(const float4*)&Bs[k][tx * TN];
            float am[4] = {a4.x, a4.y, a4.z, a4.w};
            float bn[4] = {b4.x, b4.y, b4.z, b4.w};
#pragma unroll
            for (int m = 0; m < TM; m++)
#pragma unroll
                for (int n = 0; n < TN; n++)
                    acc[m][n] = fmaf(am[m], bn[n], acc[m][n]);
        }
    }

    // epilogue
#pragma unroll
    for (int m = 0; m < TM; m++) {
        int row = rowBase + ty * TM + m;
        float4 v;
        float* vv = (float*)&v;
#pragma unroll
        for (int n = 0; n < TN; n++) {
            float bs;
            if constexpr (EXPERT) {
                bs = 0.f;
#pragma unroll
                for (int e = 0; e < E_; e++)
                    bs = fmaf(coef_s[(ty * TM + m) * E_ + e],
                              bias_s[e * BN + tx * TN + n], bs);
            } else {
                bs = bias[colBase + tx * TN + n];
            }
            float o = acc[m][n] + bs;
            if (ACT == 1) o = (o > 0.f) ? o : expm1f(o);
            vv[n] = o;
        }
        *(float4*)(C + (size_t)row * ldc + colBase + tx * TN) = v;
    }
}

// ---------------- gating head + softmax: coef = softmax(g2 @ gw3 + gb3) ----------------
__global__ __launch_bounds__(256)
void coef_kernel(const float* __restrict__ g2,
                 const float* __restrict__ gw3,   // [256, 8]
                 const float* __restrict__ gb3)   // [8]
{
    __shared__ float w_s[HG_ * 9];   // stride-9 padding: conflict-free lane reads
    for (int i = threadIdx.x; i < HG_ * E_; i += blockDim.x)
        w_s[(i / E_) * 9 + (i % E_)] = gw3[i];
    __syncthreads();

    int lane   = threadIdx.x & 31;
    int warp   = (blockIdx.x * blockDim.x + threadIdx.x) >> 5;
    int nwarps = (gridDim.x * blockDim.x) >> 5;

    for (int b = warp; b < B_; b += nwarps) {
        float acc[E_] = {};
        for (int i = lane; i < HG_; i += 32) {
            float v = g2[(size_t)b * HG_ + i];
            const float* wr = &w_s[i * 9];
#pragma unroll
            for (int e = 0; e < E_; e++) acc[e] = fmaf(v, wr[e], acc[e]);
        }
#pragma unroll
        for (int e = 0; e < E_; e++)
#pragma unroll
            for (int off = 16; off; off >>= 1)
                acc[e] += __shfl_xor_sync(0xFFFFFFFFu, acc[e], off);
        if (lane == 0) {
            float mx = -1e30f;
#pragma unroll
            for (int e = 0; e < E_; e++) { acc[e] += gb3[e]; mx = fmaxf(mx, acc[e]); }
            float s = 0.f;
#pragma unroll
            for (int e = 0; e < E_; e++) { acc[e] = expf(acc[e] - mx); s += acc[e]; }
            float inv = 1.f / s;
#pragma unroll
            for (int e = 0; e < E_; e++) g_coef[b * E_ + e] = acc[e] * inv;
        }
    }
}

// ---------------- launch ----------------
extern "C" void kernel_launch(void* const* d_in, const int* in_sizes, int n_in,
                              void* d_out, int out_size)
{
    const float* x   = (const float*)d_in[0];
    const float* z   = (const float*)d_in[1];
    const float* gw0 = (const float*)d_in[2];
    const float* gb0 = (const float*)d_in[3];
    const float* gw1 = (const float*)d_in[4];
    const float* gb1 = (const float*)d_in[5];
    const float* gw2 = (const float*)d_in[6];
    const float* gb2 = (const float*)d_in[7];
    const float* gw3 = (const float*)d_in[8];
    const float* gb3 = (const float*)d_in[9];
    const float* w0  = (const float*)d_in[10];
    const float* b0  = (const float*)d_in[11];
    const float* w1  = (const float*)d_in[12];
    const float* b1  = (const float*)d_in[13];
    const float* w2  = (const float*)d_in[14];
    const float* b2  = (const float*)d_in[15];
    float* out = (float*)d_out;

    float *xz, *g0, *g1, *g2, *h1, *h2, *coef;
    cudaGetSymbolAddress((void**)&xz,   g_xz);
    cudaGetSymbolAddress((void**)&g0,   g_g0);
    cudaGetSymbolAddress((void**)&g1,   g_g1);
    cudaGetSymbolAddress((void**)&g2,   g_g2);
    cudaGetSymbolAddress((void**)&h1,   g_h1);
    cudaGetSymbolAddress((void**)&h2,   g_h2);
    cudaGetSymbolAddress((void**)&coef, g_coef);

    pack_kernel<<<1024, 256>>>(x, z);

    // gating MLP
    gemm_kernel<64,64,16,false,1,1><<<dim3(HG_/64, B_/64), 256>>>(
        xz, DIN_, gw0, gb0, nullptr, g0, HG_, B_, HG_, DIN_);
    gemm_kernel<64,64,16,false,1,1><<<dim3(HG_/64, B_/64), 256>>>(
        g0, HG_, gw1, gb1, nullptr, g1, HG_, B_, HG_, HG_);
    gemm_kernel<64,64,16,false,1,1><<<dim3(HG_/64, B_/64), 256>>>(
        g1, HG_, gw2, gb2, nullptr, g2, HG_, B_, HG_, HG_);

    coef_kernel<<<64, 256>>>(g2, gw3, gb3);

    // expert layers: single GEMM each, K = E * IN, coef fused into A-loader
    gemm_kernel<64,64,16,true,DIN_,1><<<dim3(H_/64, B_/64), 256>>>(
        xz, DIN_, w0, b0, coef, h1, IN1_, B_, H_, E_ * DIN_);
    gemm_kernel<64,64,16,true,IN1_,1><<<dim3(H_/64, B_/64), 256>>>(
        h1, IN1_, w1, b1, coef, h2, IN1_, B_, H_, E_ * IN1_);
    gemm_kernel<64,64,16,true,IN1_,0><<<dim3(NXT_/64, B_/64), 256>>>(
        h2, IN1_, w2, b2, coef, out, NXT_, B_, NXT_, E_ * IN1_);
}

// round 3
// speedup vs baseline: 2.0864x; 2.0864x over previous
#include <cuda_runtime.h>
#include <cuda_bf16.h>
#include <math.h>
#include <stdint.h>

// Problem constants
#define B_     8192
#define OBS_   128
#define LAT_   32
#define NXT_   128
#define E_     8
#define HG_    256
#define H_     256
#define DIN_   (OBS_ + LAT_)   // 160
#define IN1_   (H_ + LAT_)     // 288

// ---------------- device scratch (no allocs allowed) ----------------
__device__ float g_xz [B_ * DIN_];
__device__ float g_g0 [B_ * HG_];
__device__ float g_g1 [B_ * HG_];
__device__ float g_g2 [B_ * HG_];
__device__ float g_h1 [B_ * IN1_];
__device__ float g_h2 [B_ * IN1_];
__device__ float g_coef[B_ * E_];
__device__ float g_w0r[(E_ * DIN_) * H_];    // tf32-rounded weights, original [K,N] layout
__device__ float g_w1r[(E_ * IN1_) * H_];
__device__ float g_w2r[(E_ * IN1_) * NXT_];

// ---------------- helpers ----------------
__device__ __forceinline__ uint32_t smem_u32(const void* p) {
    uint32_t a;
    asm("{ .reg .u64 t; cvta.to.shared.u64 t, %1; cvt.u32.u64 %0, t; }" : "=r"(a) : "l"(p));
    return a;
}
__device__ __forceinline__ uint32_t tf32u(float x) {
    uint32_t r;
    asm("cvt.rna.tf32.f32 %0, %1;" : "=r"(r) : "f"(x));
    return r;
}
#define CP_ASYNC16(dst, src) \
    asm volatile("cp.async.cg.shared.global [%0], [%1], 16;" :: "r"(dst), "l"(src) : "memory")
#define CP_COMMIT() asm volatile("cp.async.commit_group;" ::: "memory")
#define CP_WAIT0()  asm volatile("cp.async.wait_group 0;" ::: "memory")

#define MMA_TF32(d, a, b)                                                          \
    asm volatile("mma.sync.aligned.m16n8k8.row.col.f32.tf32.tf32.f32 "             \
        "{%0,%1,%2,%3}, {%4,%5,%6,%7}, {%8,%9}, {%0,%1,%2,%3};"                    \
        : "+f"((d)[0]), "+f"((d)[1]), "+f"((d)[2]), "+f"((d)[3])                   \
        : "r"((a)[0]), "r"((a)[1]), "r"((a)[2]), "r"((a)[3]),                      \
          "r"((b)[0]), "r"((b)[1]))

// ---------------- pack kernel ----------------
__global__ void pack_kernel(const float* __restrict__ x, const float* __restrict__ z)
{
    int stride = gridDim.x * blockDim.x;
    int idx = blockIdx.x * blockDim.x + threadIdx.x;
    for (int t = idx; t < B_ * DIN_; t += stride) {
        int b = t / DIN_, c = t - b * DIN_;
        g_xz[t] = (c < OBS_) ? x[b * OBS_ + c] : z[b * LAT_ + (c - OBS_)];
    }
    for (int t = idx; t < B_ * LAT_; t += stride) {
        int b = t / LAT_, c = t - b * LAT_;
        float v = z[t];
        g_h1[b * IN1_ + H_ + c] = v;
        g_h2[b * IN1_ + H_ + c] = v;
    }
}

// ---------------- elementwise tf32 rounding of weights ----------------
__global__ void wround_kernel(const float* __restrict__ w, float* __restrict__ wr, int n)
{
    int stride = gridDim.x * blockDim.x;
    for (int i = blockIdx.x * blockDim.x + threadIdx.x; i < n; i += stride)
        wr[i] = __uint_as_float(tf32u(w[i]));
}

// ---------------- SIMT tiled SGEMM (gating MLP, fp32, known-good) ----------------
template<int BM, int BN, int BK, int ACT>
__global__ __launch_bounds__(256)
void gemm_kernel(const float* __restrict__ A, int lda,
                 const float* __restrict__ W,
                 const float* __restrict__ bias,
                 float* __restrict__ C, int ldc,
                 int M, int N, int K)
{
    constexpr int TM = 4, TN = 4;
    __shared__ float As[BK][BM];
    __shared__ float Bs[BK][BN];

    const int tid = threadIdx.x;
    const int tx  = tid & ((BN / TN) - 1);
    const int ty  = tid / (BN / TN);
    const int rowBase = blockIdx.y * BM;
    const int colBase = blockIdx.x * BN;

    const int arow  = tid >> 2;
    const int ak4   = (tid & 3) * 4;
    const int brow  = tid >> 4;
    const int bcol4 = (tid & 15) * 4;

    float acc[TM][TN] = {};

    for (int kt = 0; kt < K; kt += BK) {
        float4 av = *(const float4*)(A + (size_t)(rowBase + arow) * lda + kt + ak4);
        float4 bv = *(const float4*)(W + (size_t)(kt + brow) * N + colBase + bcol4);
        __syncthreads();
        As[ak4 + 0][arow] = av.x;
        As[ak4 + 1][arow] = av.y;
        As[ak4 + 2][arow] = av.z;
        As[ak4 + 3][arow] = av.w;
        *(float4*)&Bs[brow][bcol4] = bv;
        __syncthreads();
#pragma unroll
        for (int k = 0; k < BK; k++) {
            float4 a4 = *(const float4*)&As[k][ty * TM];
            float4 b4 = *(const float4*)&Bs[k][tx * TN];
            float am[4] = {a4.x, a4.y, a4.z, a4.w};
            float bn[4] = {b4.x, b4.y, b4.z, b4.w};
#pragma unroll
            for (int m = 0; m < TM; m++)
#pragma unroll
                for (int n = 0; n < TN; n++)
                    acc[m][n] = fmaf(am[m], bn[n], acc[m][n]);
        }
    }
#pragma unroll
    for (int m = 0; m < TM; m++) {
        int row = rowBase + ty * TM + m;
        float4 v; float* vv = (float*)&v;
#pragma unroll
        for (int n = 0; n < TN; n++) {
            float o = acc[m][n] + bias[colBase + tx * TN + n];
            if (ACT == 1) o = (o > 0.f) ? o : expm1f(o);
            vv[n] = o;
        }
        *(float4*)(C + (size_t)row * ldc + colBase + tx * TN) = v;
    }
}

// ---------------- gating head + softmax ----------------
__global__ __launch_bounds__(256)
void coef_kernel(const float* __restrict__ g2,
                 const float* __restrict__ gw3, const float* __restrict__ gb3)
{
    __shared__ float w_s[HG_ * 9];
    for (int i = threadIdx.x; i < HG_ * E_; i += blockDim.x)
        w_s[(i / E_) * 9 + (i % E_)] = gw3[i];
    __syncthreads();

    int lane   = threadIdx.x & 31;
    int warp   = (blockIdx.x * blockDim.x + threadIdx.x) >> 5;
    int nwarps = (gridDim.x * blockDim.x) >> 5;

    for (int b = warp; b < B_; b += nwarps) {
        float acc[E_] = {};
        for (int i = lane; i < HG_; i += 32) {
            float v = g2[(size_t)b * HG_ + i];
            const float* wr = &w_s[i * 9];
#pragma unroll
            for (int e = 0; e < E_; e++) acc[e] = fmaf(v, wr[e], acc[e]);
        }
#pragma unroll
        for (int e = 0; e < E_; e++)
#pragma unroll
            for (int off = 16; off; off >>= 1)
                acc[e] += __shfl_xor_sync(0xFFFFFFFFu, acc[e], off);
        if (lane == 0) {
            float mx = -1e30f;
#pragma unroll
            for (int e = 0; e < E_; e++) { acc[e] += gb3[e]; mx = fmaxf(mx, acc[e]); }
            float s = 0.f;
#pragma unroll
            for (int e = 0; e < E_; e++) { acc[e] = expf(acc[e] - mx); s += acc[e]; }
            float inv = 1.f / s;
#pragma unroll
            for (int e = 0; e < E_; e++) g_coef[b * E_ + e] = acc[e] * inv;
        }
    }
}

// ---------------- expert layer via mma.sync tf32 ----------------
// C[8192, NOUT] = act( [coef-scaled A | coef] @ [[W]; [bias]] )
// Block 128x128, BK=32, 8 warps (2x4), warp tile 64x32. Double-buffered smem.
// Extra K-tile NT carries the coef/bias product (bias folded into the MMA).
template<int IN, int NOUT, int ACT>
__global__ __launch_bounds__(256, 1)
void expert_mma_kernel(const float* __restrict__ A, int lda,
                       const float* __restrict__ Wr,     // tf32-rounded [E*IN, NOUT]
                       const float* __restrict__ bias,   // [E, NOUT] fp32
                       const float* __restrict__ coef,   // [B, E]
                       float* __restrict__ Cout, int ldc)
{
    constexpr int KTOT = E_ * IN;
    constexpr int NT   = KTOT / 32;     // normal k-tiles
    constexpr int NTT  = NT + 1;        // + coef/bias tile
    constexpr int ASTR = 36;            // As row stride (floats)
    constexpr int BSTR = 136;           // Bs row stride (floats)

    extern __shared__ char smem[];
    float* coef_s = (float*)smem;                       // 128*8 floats = 4KB
    const int OFF_A0 = 4096;
    const int OFF_A1 = OFF_A0 + 128 * ASTR * 4;         // 18432 each
    const int OFF_B0 = OFF_A1 + 128 * ASTR * 4;
    const int OFF_B1 = OFF_B0 + 32 * BSTR * 4;          // 17408 each
    const int aoff[2] = {OFF_A0, OFF_A1};
    const int boff[2] = {OFF_B0, OFF_B1};

    const uint32_t sb = smem_u32(smem);
    const int tid = threadIdx.x, wid = tid >> 5, lid = tid & 31;
    const int g = lid >> 2, tig = lid & 3;
    const int m0 = blockIdx.y * 128, n0 = blockIdx.x * 128;
    const int rbase = (wid >> 2) * 64;    // warp M offset (0 or 64)
    const int cbase = (wid & 3) * 32;     // warp N offset

    // staging indices
    const int arow = tid >> 1;            // 0..127
    const int akq  = (tid & 1) * 16;      // 0 or 16
    const int bk   = tid >> 3;            // 0..31
    const int bc0  = (tid & 7) * 16;      // 0..112

    // load coef tile
    for (int i = tid; i < 128 * E_; i += 256) coef_s[i] = coef[m0 * E_ + i];
    __syncthreads();

    // ---- staging lambdas ----
    auto issue_cpasync_B = [&](int t, int buf) {
        const int k0 = t * 32;
#pragma unroll
        for (int i = 0; i < 4; i++) {
            int id  = tid + 256 * i;
            int k   = id >> 5;
            int c4  = (id & 31) * 4;
            uint32_t dst = sb + boff[buf] + (k * BSTR + c4) * 4;
            const float* src = Wr + (size_t)(k0 + k) * NOUT + n0 + c4;
            CP_ASYNC16(dst, src);
        }
        CP_COMMIT();
    };
    auto load_A_regs = [&](int t, float4* pa) {
        const int k0 = t * 32;
        const int e  = k0 / IN;
        const int i0 = k0 - e * IN;
        const float* ap = A + (size_t)(m0 + arow) * lda + i0 + akq;
#pragma unroll
        for (int a = 0; a < 4; a++) pa[a] = *(const float4*)(ap + 4 * a);
    };
    auto store_A_smem = [&](int t, int buf, const float4* pa) {
        const int k0 = t * 32;
        const int e  = k0 / IN;
        const float s = coef_s[arow * E_ + e];
        float* As = (float*)(smem + aoff[buf]);
#pragma unroll
        for (int a = 0; a < 4; a++) {
            uint4 u;
            u.x = tf32u(pa[a].x * s); u.y = tf32u(pa[a].y * s);
            u.z = tf32u(pa[a].z * s); u.w = tf32u(pa[a].w * s);
            *(uint4*)(As + arow * ASTR + akq + 4 * a) = u;
        }
    };
    auto stage_special = [&](int buf) {
        // A: columns j<8 hold coef[row, j], rest zero
        float* As = (float*)(smem + aoff[buf]);
#pragma unroll
        for (int a = 0; a < 4; a++) {
            uint4 u;
            uint32_t* uu = (uint32_t*)&u;
#pragma unroll
            for (int q = 0; q < 4; q++) {
                int k = akq + 4 * a + q;
                uu[q] = (k < E_) ? tf32u(coef_s[arow * E_ + k]) : 0u;
            }
            *(uint4*)(As + arow * ASTR + akq + 4 * a) = u;
        }
        // B: rows j<8 hold bias[j, col], rest zero
        float* Bs = (float*)(smem + boff[buf]);
#pragma unroll
        for (int j = 0; j < 16; j += 4) {
            uint4 u;
            uint32_t* uu = (uint32_t*)&u;
#pragma unroll
            for (int q = 0; q < 4; q++)
                uu[q] = (bk < E_) ? tf32u(bias[bk * NOUT + n0 + bc0 + j + q]) : 0u;
            *(uint4*)(Bs + bk * BSTR + bc0 + j) = u;
        }
    };

    // ---- accumulators ----
    float acc[4][4][4] = {};

    // ---- prologue: stage tile 0 into buf 0 ----
    {
        issue_cpasync_B(0, 0);
        float4 pa[4];
        load_A_regs(0, pa);
        store_A_smem(0, 0, pa);
        CP_WAIT0();
    }
    __syncthreads();

    // ---- main loop ----
    for (int t = 0; t < NTT; t++) {
        const int buf = t & 1;
        const bool hasNext = (t + 1 < NTT);
        const bool nextNormal = (t + 1 < NT);

        float4 pa[4];
        if (hasNext && nextNormal) {
            issue_cpasync_B(t + 1, buf ^ 1);
            load_A_regs(t + 1, pa);
        }

        // compute on buf
        {
            const uint32_t* Asu = (const uint32_t*)(smem + aoff[buf]);
            const uint32_t* Bsu = (const uint32_t*)(smem + boff[buf]);
#pragma unroll
            for (int k8 = 0; k8 < 4; k8++) {
                uint32_t af[4][4], bf[4][2];
#pragma unroll
                for (int mt = 0; mt < 4; mt++) {
                    const int r0 = rbase + mt * 16 + g;
                    const int kk = k8 * 8 + tig;
                    af[mt][0] = Asu[r0 * ASTR + kk];
                    af[mt][1] = Asu[(r0 + 8) * ASTR + kk];
                    af[mt][2] = Asu[r0 * ASTR + kk + 4];
                    af[mt][3] = Asu[(r0 + 8) * ASTR + kk + 4];
                }
#pragma unroll
                for (int nt = 0; nt < 4; nt++) {
                    const int c0 = cbase + nt * 8 + g;
                    bf[nt][0] = Bsu[(k8 * 8 + tig) * BSTR + c0];
                    bf[nt][1] = Bsu[(k8 * 8 + tig + 4) * BSTR + c0];
                }
#pragma unroll
                for (int mt = 0; mt < 4; mt++)
#pragma unroll
                    for (int nt = 0; nt < 4; nt++)
                        MMA_TF32(acc[mt][nt], af[mt], bf[nt]);
            }
        }

        if (hasNext) {
            if (nextNormal) store_A_smem(t + 1, buf ^ 1, pa);
            else            stage_special(buf ^ 1);
            CP_WAIT0();
        }
        __syncthreads();
    }

    // ---- epilogue: ELU + store (bias already folded into MMA) ----
#pragma unroll
    for (int mt = 0; mt < 4; mt++) {
        const int r = m0 + rbase + mt * 16 + g;
#pragma unroll
        for (int nt = 0; nt < 4; nt++) {
            const int c = n0 + cbase + nt * 8 + 2 * tig;
            float2 v0, v1;
            v0.x = acc[mt][nt][0]; v0.y = acc[mt][nt][1];
            v1.x = acc[mt][nt][2]; v1.y = acc[mt][nt][3];
            if (ACT == 1) {
                v0.x = (v0.x > 0.f) ? v0.x : expm1f(v0.x);
                v0.y = (v0.y > 0.f) ? v0.y : expm1f(v0.y);
                v1.x = (v1.x > 0.f) ? v1.x : expm1f(v1.x);
                v1.y = (v1.y > 0.f) ? v1.y : expm1f(v1.y);
            }
            *(float2*)(Cout + (size_t)r * ldc + c)       = v0;
            *(float2*)(Cout + (size_t)(r + 8) * ldc + c) = v1;
        }
    }
}

// ---------------- launch ----------------
extern "C" void kernel_launch(void* const* d_in, const int* in_sizes, int n_in,
                              void* d_out, int out_size)
{
    const float* x   = (const float*)d_in[0];
    const float* z   = (const float*)d_in[1];
    const float* gw0 = (const float*)d_in[2];
    const float* gb0 = (const float*)d_in[3];
    const float* gw1 = (const float*)d_in[4];
    const float* gb1 = (const float*)d_in[5];
    const float* gw2 = (const float*)d_in[6];
    const float* gb2 = (const float*)d_in[7];
    const float* gw3 = (const float*)d_in[8];
    const float* gb3 = (const float*)d_in[9];
    const float* w0  = (const float*)d_in[10];
    const float* b0  = (const float*)d_in[11];
    const float* w1  = (const float*)d_in[12];
    const float* b1  = (const float*)d_in[13];
    const float* w2  = (const float*)d_in[14];
    const float* b2  = (const float*)d_in[15];
    float* out = (float*)d_out;

    float *xz, *g0, *g1, *g2, *h1, *h2, *coef, *w0r, *w1r, *w2r;
    cudaGetSymbolAddress((void**)&xz,   g_xz);
    cudaGetSymbolAddress((void**)&g0,   g_g0);
    cudaGetSymbolAddress((void**)&g1,   g_g1);
    cudaGetSymbolAddress((void**)&g2,   g_g2);
    cudaGetSymbolAddress((void**)&h1,   g_h1);
    cudaGetSymbolAddress((void**)&h2,   g_h2);
    cudaGetSymbolAddress((void**)&coef, g_coef);
    cudaGetSymbolAddress((void**)&w0r,  g_w0r);
    cudaGetSymbolAddress((void**)&w1r,  g_w1r);
    cudaGetSymbolAddress((void**)&w2r,  g_w2r);

    // smem: coef 4KB + 2*A(18KB) + 2*B(17KB)
    const int smem_bytes = 4096 + 2 * (128 * 36 * 4) + 2 * (32 * 136 * 4);  // 75776
    cudaFuncSetAttribute(expert_mma_kernel<DIN_, H_,   1>,
                         cudaFuncAttributeMaxDynamicSharedMemorySize, smem_bytes);
    cudaFuncSetAttribute(expert_mma_kernel<IN1_, H_,   1>,
                         cudaFuncAttributeMaxDynamicSharedMemorySize, smem_bytes);
    cudaFuncSetAttribute(expert_mma_kernel<IN1_, NXT_, 0>,
                         cudaFuncAttributeMaxDynamicSharedMemorySize, smem_bytes);

    pack_kernel<<<1024, 256>>>(x, z);

    // tf32-round weights (layout unchanged)
    wround_kernel<<<640, 256>>>(w0, w0r, E_ * DIN_ * H_);
    wround_kernel<<<1152, 256>>>(w1, w1r, E_ * IN1_ * H_);
    wround_kernel<<<576, 256>>>(w2, w2r, E_ * IN1_ * NXT_);

    // gating MLP (fp32 SIMT)
    gemm_kernel<64,64,16,1><<<dim3(HG_/64, B_/64), 256>>>(xz, DIN_, gw0, gb0, g0, HG_, B_, HG_, DIN_);
    gemm_kernel<64,64,16,1><<<dim3(HG_/64, B_/64), 256>>>(g0, HG_,  gw1, gb1, g1, HG_, B_, HG_, HG_);
    gemm_kernel<64,64,16,1><<<dim3(HG_/64, B_/64), 256>>>(g1, HG_,  gw2, gb2, g2, HG_, B_, HG_, HG_);
    coef_kernel<<<64, 256>>>(g2, gw3, gb3);

    // expert layers on tensor cores (mma.sync tf32)
    expert_mma_kernel<DIN_, H_,   1><<<dim3(H_/128,   B_/128), 256, smem_bytes>>>(
        xz, DIN_, w0r, b0, coef, h1, IN1_);
    expert_mma_kernel<IN1_, H_,   1><<<dim3(H_/128,   B_/128), 256, smem_bytes>>>(
        h1, IN1_, w1r, b1, coef, h2, IN1_);
    expert_mma_kernel<IN1_, NXT_, 0><<<dim3(NXT_/128, B_/128), 256, smem_bytes>>>(
        h2, IN1_, w2r, b2, coef, out, NXT_);
}

// round 4
// speedup vs baseline: 2.0894x; 1.0014x over previous
#include <cuda_runtime.h>
#include <cuda_bf16.h>
#include <math.h>
#include <stdint.h>

// Problem constants
#define B_     8192
#define OBS_   128
#define LAT_   32
#define NXT_   128
#define E_     8
#define HG_    256
#define H_     256
#define DIN_   (OBS_ + LAT_)   // 160
#define IN1_   (H_ + LAT_)     // 288

// ---------------- device scratch (no allocs allowed) ----------------
__device__ float g_xz [B_ * DIN_];
__device__ float g_g0 [B_ * HG_];
__device__ float g_g1 [B_ * HG_];
__device__ float g_g2 [B_ * HG_];
__device__ float g_h1 [B_ * IN1_];
__device__ float g_h2 [B_ * IN1_];
__device__ float g_coef[B_ * E_];
__device__ float g_w0r[(E_ * DIN_) * H_];    // tf32-rounded weights, original [K,N] layout
__device__ float g_w1r[(E_ * IN1_) * H_];
__device__ float g_w2r[(E_ * IN1_) * NXT_];

// ---------------- helpers ----------------
__device__ __forceinline__ uint32_t smem_u32(const void* p) {
    uint32_t a;
    asm("{ .reg .u64 t; cvta.to.shared.u64 t, %1; cvt.u32.u64 %0, t; }" : "=r"(a) : "l"(p));
    return a;
}
__device__ __forceinline__ uint32_t tf32u(float x) {
    uint32_t r;
    asm("cvt.rna.tf32.f32 %0, %1;" : "=r"(r) : "f"(x));
    return r;
}
#define CP_ASYNC16(dst, src) \
    asm volatile("cp.async.cg.shared.global [%0], [%1], 16;" :: "r"(dst), "l"(src) : "memory")
#define CP_COMMIT() asm volatile("cp.async.commit_group;" ::: "memory")
#define CP_WAIT0()  asm volatile("cp.async.wait_group 0;" ::: "memory")

#define MMA_TF32(d, a, b)                                                          \
    asm volatile("mma.sync.aligned.m16n8k8.row.col.f32.tf32.tf32.f32 "             \
        "{%0,%1,%2,%3}, {%4,%5,%6,%7}, {%8,%9}, {%0,%1,%2,%3};"                    \
        : "+f"((d)[0]), "+f"((d)[1]), "+f"((d)[2]), "+f"((d)[3])                   \
        : "r"((a)[0]), "r"((a)[1]), "r"((a)[2]), "r"((a)[3]),                      \
          "r"((b)[0]), "r"((b)[1]))

// ---------------- pack kernel ----------------
__global__ void pack_kernel(const float* __restrict__ x, const float* __restrict__ z)
{
    int stride = gridDim.x * blockDim.x;
    int idx = blockIdx.x * blockDim.x + threadIdx.x;
    for (int t = idx; t < B_ * DIN_; t += stride) {
        int b = t / DIN_, c = t - b * DIN_;
        g_xz[t] = (c < OBS_) ? x[b * OBS_ + c] : z[b * LAT_ + (c - OBS_)];
    }
    for (int t = idx; t < B_ * LAT_; t += stride) {
        int b = t / LAT_, c = t - b * LAT_;
        float v = z[t];
        g_h1[b * IN1_ + H_ + c] = v;
        g_h2[b * IN1_ + H_ + c] = v;
    }
}

// ---------------- elementwise tf32 rounding of weights ----------------
__global__ void wround_kernel(const float* __restrict__ w, float* __restrict__ wr, int n)
{
    int stride = gridDim.x * blockDim.x;
    for (int i = blockIdx.x * blockDim.x + threadIdx.x; i < n; i += stride)
        wr[i] = __uint_as_float(tf32u(w[i]));
}

// ---------------- SIMT tiled SGEMM (gating MLP, fp32, known-good) ----------------
template<int BM, int BN, int BK, int ACT>
__global__ __launch_bounds__(256)
void gemm_kernel(const float* __restrict__ A, int lda,
                 const float* __restrict__ W,
                 const float* __restrict__ bias,
                 float* __restrict__ C, int ldc,
                 int M, int N, int K)
{
    constexpr int TM = 4, TN = 4;
    __shared__ float As[BK][BM];
    __shared__ float Bs[BK][BN];

    const int tid = threadIdx.x;
    const int tx  = tid & ((BN / TN) - 1);
    const int ty  = tid / (BN / TN);
    const int rowBase = blockIdx.y * BM;
    const int colBase = blockIdx.x * BN;

    const int arow  = tid >> 2;
    const int ak4   = (tid & 3) * 4;
    const int brow  = tid >> 4;
    const int bcol4 = (tid & 15) * 4;

    float acc[TM][TN] = {};

    for (int kt = 0; kt < K; kt += BK) {
        float4 av = *(const float4*)(A + (size_t)(rowBase + arow) * lda + kt + ak4);
        float4 bv = *(const float4*)(W + (size_t)(kt + brow) * N + colBase + bcol4);
        __syncthreads();
        As[ak4 + 0][arow] = av.x;
        As[ak4 + 1][arow] = av.y;
        As[ak4 + 2][arow] = av.z;
        As[ak4 + 3][arow] = av.w;
        *(float4*)&Bs[brow][bcol4] = bv;
        __syncthreads();
#pragma unroll
        for (int k = 0; k < BK; k++) {
            float4 a4 = *(const float4*)&As[k][ty * TM];
            float4 b4 = *(const float4*)&Bs[k][tx * TN];
            float am[4] = {a4.x, a4.y, a4.z, a4.w};
            float bn[4] = {b4.x, b4.y, b4.z, b4.w};
#pragma unroll
            for (int m = 0; m < TM; m++)
#pragma unroll
                for (int n = 0; n < TN; n++)
                    acc[m][n] = fmaf(am[m], bn[n], acc[m][n]);
        }
    }
#pragma unroll
    for (int m = 0; m < TM; m++) {
        int row = rowBase + ty * TM + m;
        float4 v; float* vv = (float*)&v;
#pragma unroll
        for (int n = 0; n < TN; n++) {
            float o = acc[m][n] + bias[colBase + tx * TN + n];
            if (ACT == 1) o = (o > 0.f) ? o : expm1f(o);
            vv[n] = o;
        }
        *(float4*)(C + (size_t)row * ldc + colBase + tx * TN) = v;
    }
}

// ---------------- gating head + softmax ----------------
__global__ __launch_bounds__(256)
void coef_kernel(const float* __restrict__ g2,
                 const float* __restrict__ gw3, const float* __restrict__ gb3)
{
    __shared__ float w_s[HG_ * 9];
    for (int i = threadIdx.x; i < HG_ * E_; i += blockDim.x)
        w_s[(i / E_) * 9 + (i % E_)] = gw3[i];
    __syncthreads();

    int lane   = threadIdx.x & 31;
    int warp   = (blockIdx.x * blockDim.x + threadIdx.x) >> 5;
    int nwarps = (gridDim.x * blockDim.x) >> 5;

    for (int b = warp; b < B_; b += nwarps) {
        float acc[E_] = {};
        for (int i = lane; i < HG_; i += 32) {
            float v = g2[(size_t)b * HG_ + i];
            const float* wr = &w_s[i * 9];
#pragma unroll
            for (int e = 0; e < E_; e++) acc[e] = fmaf(v, wr[e], acc[e]);
        }
#pragma unroll
        for (int e = 0; e < E_; e++)
#pragma unroll
            for (int off = 16; off; off >>= 1)
                acc[e] += __shfl_xor_sync(0xFFFFFFFFu, acc[e], off);
        if (lane == 0) {
            float mx = -1e30f;
#pragma unroll
            for (int e = 0; e < E_; e++) { acc[e] += gb3[e]; mx = fmaxf(mx, acc[e]); }
            float s = 0.f;
#pragma unroll
            for (int e = 0; e < E_; e++) { acc[e] = expf(acc[e] - mx); s += acc[e]; }
            float inv = 1.f / s;
#pragma unroll
            for (int e = 0; e < E_; e++) g_coef[b * E_ + e] = acc[e] * inv;
        }
    }
}

// ---------------- expert layer via mma.sync tf32 ----------------
// C[8192, NOUT] = act( [coef-scaled A | coef] @ [[W]; [bias]] )
// Block 128x128, BK=32, 8 warps (2x4), warp tile 64x32. Double-buffered smem.
// Extra K-tile NT carries the coef/bias product (bias folded into the MMA).
template<int IN, int NOUT, int ACT>
__global__ __launch_bounds__(256, 1)
void expert_mma_kernel(const float* __restrict__ A, int lda,
                       const float* __restrict__ Wr,     // tf32-rounded [E*IN, NOUT]
                       const float* __restrict__ bias,   // [E, NOUT] fp32
                       const float* __restrict__ coef,   // [B, E]
                       float* __restrict__ Cout, int ldc)
{
    constexpr int KTOT = E_ * IN;
    constexpr int NT   = KTOT / 32;     // normal k-tiles
    constexpr int NTT  = NT + 1;        // + coef/bias tile
    constexpr int ASTR = 36;            // As row stride (floats)
    constexpr int BSTR = 136;           // Bs row stride (floats)

    extern __shared__ char smem[];
    float* coef_s = (float*)smem;                       // 128*8 floats = 4KB
    const int OFF_A0 = 4096;
    const int OFF_A1 = OFF_A0 + 128 * ASTR * 4;         // 18432 each
    const int OFF_B0 = OFF_A1 + 128 * ASTR * 4;
    const int OFF_B1 = OFF_B0 + 32 * BSTR * 4;          // 17408 each
    const int aoff[2] = {OFF_A0, OFF_A1};
    const int boff[2] = {OFF_B0, OFF_B1};

    const uint32_t sb = smem_u32(smem);
    const int tid = threadIdx.x, wid = tid >> 5, lid = tid & 31;
    const int g = lid >> 2, tig = lid & 3;
    const int m0 = blockIdx.y * 128, n0 = blockIdx.x * 128;
    const int rbase = (wid >> 2) * 64;    // warp M offset (0 or 64)
    const int cbase = (wid & 3) * 32;     // warp N offset

    // staging indices
    const int arow = tid >> 1;            // 0..127
    const int akq  = (tid & 1) * 16;      // 0 or 16
    const int bk   = tid >> 3;            // 0..31
    const int bc0  = (tid & 7) * 16;      // 0..112

    // load coef tile
    for (int i = tid; i < 128 * E_; i += 256) coef_s[i] = coef[m0 * E_ + i];
    __syncthreads();

    // ---- staging lambdas ----
    auto issue_cpasync_B = [&](int t, int buf) {
        const int k0 = t * 32;
#pragma unroll
        for (int i = 0; i < 4; i++) {
            int id  = tid + 256 * i;
            int k   = id >> 5;
            int c4  = (id & 31) * 4;
            uint32_t dst = sb + boff[buf] + (k * BSTR + c4) * 4;
            const float* src = Wr + (size_t)(k0 + k) * NOUT + n0 + c4;
            CP_ASYNC16(dst, src);
        }
        CP_COMMIT();
    };
    auto load_A_regs = [&](int t, float4* pa) {
        const int k0 = t * 32;
        const int e  = k0 / IN;
        const int i0 = k0 - e * IN;
        const float* ap = A + (size_t)(m0 + arow) * lda + i0 + akq;
#pragma unroll
        for (int a = 0; a < 4; a++) pa[a] = *(const float4*)(ap + 4 * a);
    };
    auto store_A_smem = [&](int t, int buf, const float4* pa) {
        const int k0 = t * 32;
        const int e  = k0 / IN;
        const float s = coef_s[arow * E_ + e];
        float* As = (float*)(smem + aoff[buf]);
#pragma unroll
        for (int a = 0; a < 4; a++) {
            uint4 u;
            u.x = tf32u(pa[a].x * s); u.y = tf32u(pa[a].y * s);
            u.z = tf32u(pa[a].z * s); u.w = tf32u(pa[a].w * s);
            *(uint4*)(As + arow * ASTR + akq + 4 * a) = u;
        }
    };
    auto stage_special = [&](int buf) {
        // A: columns j<8 hold coef[row, j], rest zero
        float* As = (float*)(smem + aoff[buf]);
#pragma unroll
        for (int a = 0; a < 4; a++) {
            uint4 u;
            uint32_t* uu = (uint32_t*)&u;
#pragma unroll
            for (int q = 0; q < 4; q++) {
                int k = akq + 4 * a + q;
                uu[q] = (k < E_) ? tf32u(coef_s[arow * E_ + k]) : 0u;
            }
            *(uint4*)(As + arow * ASTR + akq + 4 * a) = u;
        }
        // B: rows j<8 hold bias[j, col], rest zero
        float* Bs = (float*)(smem + boff[buf]);
#pragma unroll
        for (int j = 0; j < 16; j += 4) {
            uint4 u;
            uint32_t* uu = (uint32_t*)&u;
#pragma unroll
            for (int q = 0; q < 4; q++)
                uu[q] = (bk < E_) ? tf32u(bias[bk * NOUT + n0 + bc0 + j + q]) : 0u;
            *(uint4*)(Bs + bk * BSTR + bc0 + j) = u;
        }
    };

    // ---- accumulators ----
    float acc[4][4][4] = {};

    // ---- prologue: stage tile 0 into buf 0 ----
    {
        issue_cpasync_B(0, 0);
        float4 pa[4];
        load_A_regs(0, pa);
        store_A_smem(0, 0, pa);
        CP_WAIT0();
    }
    __syncthreads();

    // ---- main loop ----
    for (int t = 0; t < NTT; t++) {
        const int buf = t & 1;
        const bool hasNext = (t + 1 < NTT);
        const bool nextNormal = (t + 1 < NT);

        float4 pa[4];
        if (hasNext && nextNormal) {
            issue_cpasync_B(t + 1, buf ^ 1);
            load_A_regs(t + 1, pa);
        }

        // compute on buf
        {
            const uint32_t* Asu = (const uint32_t*)(smem + aoff[buf]);
            const uint32_t* Bsu = (const uint32_t*)(smem + boff[buf]);
#pragma unroll
            for (int k8 = 0; k8 < 4; k8++) {
                uint32_t af[4][4], bf[4][2];
#pragma unroll
                for (int mt = 0; mt < 4; mt++) {
                    const int r0 = rbase + mt * 16 + g;
                    const int kk = k8 * 8 + tig;
                    af[mt][0] = Asu[r0 * ASTR + kk];
                    af[mt][1] = Asu[(r0 + 8) * ASTR + kk];
                    af[mt][2] = Asu[r0 * ASTR + kk + 4];
                    af[mt][3] = Asu[(r0 + 8) * ASTR + kk + 4];
                }
#pragma unroll
                for (int nt = 0; nt < 4; nt++) {
                    const int c0 = cbase + nt * 8 + g;
                    bf[nt][0] = Bsu[(k8 * 8 + tig) * BSTR + c0];
                    bf[nt][1] = Bsu[(k8 * 8 + tig + 4) * BSTR + c0];
                }
#pragma unroll
                for (int mt = 0; mt < 4; mt++)
#pragma unroll
                    for (int nt = 0; nt < 4; nt++)
                        MMA_TF32(acc[mt][nt], af[mt], bf[nt]);
            }
        }

        if (hasNext) {
            if (nextNormal) store_A_smem(t + 1, buf ^ 1, pa);
            else            stage_special(buf ^ 1);
            CP_WAIT0();
        }
        __syncthreads();
    }

    // ---- epilogue: ELU + store (bias already folded into MMA) ----
#pragma unroll
    for (int mt = 0; mt < 4; mt++) {
        const int r = m0 + rbase + mt * 16 + g;
#pragma unroll
        for (int nt = 0; nt < 4; nt++) {
            const int c = n0 + cbase + nt * 8 + 2 * tig;
            float2 v0, v1;
            v0.x = acc[mt][nt][0]; v0.y = acc[mt][nt][1];
            v1.x = acc[mt][nt][2]; v1.y = acc[mt][nt][3];
            if (ACT == 1) {
                v0.x = (v0.x > 0.f) ? v0.x : expm1f(v0.x);
                v0.y = (v0.y > 0.f) ? v0.y : expm1f(v0.y);
                v1.x = (v1.x > 0.f) ? v1.x : expm1f(v1.x);
                v1.y = (v1.y > 0.f) ? v1.y : expm1f(v1.y);
            }
            *(float2*)(Cout + (size_t)r * ldc + c)       = v0;
            *(float2*)(Cout + (size_t)(r + 8) * ldc + c) = v1;
        }
    }
}

// ---------------- launch ----------------
extern "C" void kernel_launch(void* const* d_in, const int* in_sizes, int n_in,
                              void* d_out, int out_size)
{
    const float* x   = (const float*)d_in[0];
    const float* z   = (const float*)d_in[1];
    const float* gw0 = (const float*)d_in[2];
    const float* gb0 = (const float*)d_in[3];
    const float* gw1 = (const float*)d_in[4];
    const float* gb1 = (const float*)d_in[5];
    const float* gw2 = (const float*)d_in[6];
    const float* gb2 = (const float*)d_in[7];
    const float* gw3 = (const float*)d_in[8];
    const float* gb3 = (const float*)d_in[9];
    const float* w0  = (const float*)d_in[10];
    const float* b0  = (const float*)d_in[11];
    const float* w1  = (const float*)d_in[12];
    const float* b1  = (const float*)d_in[13];
    const float* w2  = (const float*)d_in[14];
    const float* b2  = (const float*)d_in[15];
    float* out = (float*)d_out;

    float *xz, *g0, *g1, *g2, *h1, *h2, *coef, *w0r, *w1r, *w2r;
    cudaGetSymbolAddress((void**)&xz,   g_xz);
    cudaGetSymbolAddress((void**)&g0,   g_g0);
    cudaGetSymbolAddress((void**)&g1,   g_g1);
    cudaGetSymbolAddress((void**)&g2,   g_g2);
    cudaGetSymbolAddress((void**)&h1,   g_h1);
    cudaGetSymbolAddress((void**)&h2,   g_h2);
    cudaGetSymbolAddress((void**)&coef, g_coef);
    cudaGetSymbolAddress((void**)&w0r,  g_w0r);
    cudaGetSymbolAddress((void**)&w1r,  g_w1r);
    cudaGetSymbolAddress((void**)&w2r,  g_w2r);

    // smem: coef 4KB + 2*A(18KB) + 2*B(17KB)
    const int smem_bytes = 4096 + 2 * (128 * 36 * 4) + 2 * (32 * 136 * 4);  // 75776
    cudaFuncSetAttribute(expert_mma_kernel<DIN_, H_,   1>,
                         cudaFuncAttributeMaxDynamicSharedMemorySize, smem_bytes);
    cudaFuncSetAttribute(expert_mma_kernel<IN1_, H_,   1>,
                         cudaFuncAttributeMaxDynamicSharedMemorySize, smem_bytes);
    cudaFuncSetAttribute(expert_mma_kernel<IN1_, NXT_, 0>,
                         cudaFuncAttributeMaxDynamicSharedMemorySize, smem_bytes);

    pack_kernel<<<1024, 256>>>(x, z);

    // tf32-round weights (layout unchanged)
    wround_kernel<<<640, 256>>>(w0, w0r, E_ * DIN_ * H_);
    wround_kernel<<<1152, 256>>>(w1, w1r, E_ * IN1_ * H_);
    wround_kernel<<<576, 256>>>(w2, w2r, E_ * IN1_ * NXT_);

    // gating MLP (fp32 SIMT)
    gemm_kernel<64,64,16,1><<<dim3(HG_/64, B_/64), 256>>>(xz, DIN_, gw0, gb0, g0, HG_, B_, HG_, DIN_);
    gemm_kernel<64,64,16,1><<<dim3(HG_/64, B_/64), 256>>>(g0, HG_,  gw1, gb1, g1, HG_, B_, HG_, HG_);
    gemm_kernel<64,64,16,1><<<dim3(HG_/64, B_/64), 256>>>(g1, HG_,  gw2, gb2, g2, HG_, B_, HG_, HG_);
    coef_kernel<<<64, 256>>>(g2, gw3, gb3);

    // expert layers on tensor cores (mma.sync tf32)
    expert_mma_kernel<DIN_, H_,   1><<<dim3(H_/128,   B_/128), 256, smem_bytes>>>(
        xz, DIN_, w0r, b0, coef, h1, IN1_);
    expert_mma_kernel<IN1_, H_,   1><<<dim3(H_/128,   B_/128), 256, smem_bytes>>>(
        h1, IN1_, w1r, b1, coef, h2, IN1_);
    expert_mma_kernel<IN1_, NXT_, 0><<<dim3(NXT_/128, B_/128), 256, smem_bytes>>>(
        h2, IN1_, w2r, b2, coef, out, NXT_);
}